// round 3
// baseline (speedup 1.0000x reference)
#include <cuda_runtime.h>
#include <math.h>

#define B_  64
#define S_  2048
#define U_  1024
#define M_  (B_ * S_)   // 131072

// ---------------- scratch (no allocs allowed; __device__ globals) ----------
__device__ float g_Ws[B_ * U_];      // 256 KB : s_prev @ W_w + W_b
__device__ float g_scores[M_];       // 512 KB : pre-softmax scores

// ---------------- K0: init scratch + zero context region -------------------
__global__ void k_init(const float* __restrict__ Wb,
                       const float* __restrict__ Vb,
                       float* __restrict__ ctx_out) {
    int i = blockIdx.x * blockDim.x + threadIdx.x;   // 0 .. 131071
    if (i < B_ * U_) {
        g_Ws[i]   = Wb[i & (U_ - 1)];
        ctx_out[i] = 0.0f;
    }
    if (i < M_) g_scores[i] = Vb[0];
}

// ---------------- K1: Ws += s_prev @ W_w  (k-split, atomics) ----------------
// grid (8 u-chunks, 8 k-chunks), 128 threads. Each thread owns one u column.
__global__ void __launch_bounds__(128) k_ws(const float* __restrict__ s_prev,
                                            const float* __restrict__ Ww) {
    __shared__ float s_sm[B_][128];           // 32 KB: s_prev[:, kchunk]
    const int tid = threadIdx.x;
    const int u   = blockIdx.x * 128 + tid;
    const int k0  = blockIdx.y * 128;

    // load s_prev[64][128] chunk: 8192 floats / 128 threads = 64 each
    for (int j = 0; j < 64; j++) {
        int idx = tid + 128 * j;              // 0..8191
        int b   = idx >> 7;
        int kk  = idx & 127;
        s_sm[b][kk] = s_prev[b * U_ + k0 + kk];
    }
    __syncthreads();

    float acc[B_];
    #pragma unroll
    for (int b = 0; b < B_; b++) acc[b] = 0.0f;

    for (int kk = 0; kk < 128; kk++) {
        float w = Ww[(k0 + kk) * U_ + u];
        #pragma unroll
        for (int b = 0; b < B_; b++) acc[b] += s_sm[b][kk] * w;
    }
    #pragma unroll
    for (int b = 0; b < B_; b++) atomicAdd(&g_Ws[b * U_ + u], acc[b]);
}

// ---------------- K2: fused scores GEMM ------------------------------------
// C = HS[M,K] @ U_w[K,N]; epilogue: score[row] += sum_n tanh(C+Ws+Ub)*Vw
// Tile: BM=128, BN=64, BK=16, 256 threads, 8x4 per thread.
#define BM 128
#define BN 64
#define BK 16

__global__ void __launch_bounds__(256) k_scores(const float* __restrict__ HS,
                                                const float* __restrict__ Uw,
                                                const float* __restrict__ Ub,
                                                const float* __restrict__ Vw) {
    __shared__ __align__(16) float As[BK][BM];   // 8 KB
    __shared__ __align__(16) float Bs[BK][BN];   // 4 KB
    __shared__ float sWs[BN], sUb[BN], sVw[BN];

    const int tid  = threadIdx.x;
    const int nblk = blockIdx.x;        // 0..15
    const int mblk = blockIdx.y;        // 0..1023
    const int row0 = mblk * BM;
    const int col0 = nblk * BN;
    const int b    = row0 / S_;         // tile fully inside one batch (128|2048)

    if (tid < BN) {
        sWs[tid] = g_Ws[b * U_ + col0 + tid];
        sUb[tid] = Ub[col0 + tid];
        sVw[tid] = Vw[col0 + tid];
    }

    const int tx = tid & 15;            // n dim (16 x 4 = 64)
    const int ty = tid >> 4;            // m dim (16 x 8 = 128)

    float acc[8][4];
    #pragma unroll
    for (int i = 0; i < 8; i++)
        #pragma unroll
        for (int j = 0; j < 4; j++) acc[i][j] = 0.0f;

    const float* Aptr = HS + (size_t)row0 * U_;
    const float* Bptr = Uw + col0;

    for (int k0 = 0; k0 < U_; k0 += BK) {
        __syncthreads();
        // A tile: 128x16 = 512 float4, 2 per thread; store transposed
        #pragma unroll
        for (int r = 0; r < 2; r++) {
            int fa   = tid + 256 * r;
            int arow = fa >> 2;
            int kq   = (fa & 3) * 4;
            float4 v = *(const float4*)(Aptr + (size_t)arow * U_ + k0 + kq);
            As[kq + 0][arow] = v.x;
            As[kq + 1][arow] = v.y;
            As[kq + 2][arow] = v.z;
            As[kq + 3][arow] = v.w;
        }
        // B tile: 16x64 = 256 float4, 1 per thread
        {
            int brow = tid >> 4;              // 0..15
            int bq   = (tid & 15) * 4;        // 0..60
            float4 v = *(const float4*)(Bptr + (size_t)(k0 + brow) * U_ + bq);
            *(float4*)&Bs[brow][bq] = v;
        }
        __syncthreads();

        #pragma unroll
        for (int kk = 0; kk < BK; kk++) {
            float4 a0 = *(const float4*)&As[kk][ty * 8];
            float4 a1 = *(const float4*)&As[kk][ty * 8 + 4];
            float4 bb = *(const float4*)&Bs[kk][tx * 4];
            float av[8] = {a0.x, a0.y, a0.z, a0.w, a1.x, a1.y, a1.z, a1.w};
            float bv[4] = {bb.x, bb.y, bb.z, bb.w};
            #pragma unroll
            for (int i = 0; i < 8; i++)
                #pragma unroll
                for (int j = 0; j < 4; j++) acc[i][j] += av[i] * bv[j];
        }
    }

    // epilogue: tanh + dot with Vw, reduce across the 16 tx lanes per row
    #pragma unroll
    for (int i = 0; i < 8; i++) {
        float p = 0.0f;
        #pragma unroll
        for (int j = 0; j < 4; j++) {
            int n = tx * 4 + j;
            p += tanhf(acc[i][j] + sWs[n] + sUb[n]) * sVw[n];
        }
        #pragma unroll
        for (int off = 8; off > 0; off >>= 1)
            p += __shfl_down_sync(0xffffffffu, p, off, 16);
        if (tx == 0) atomicAdd(&g_scores[row0 + ty * 8 + i], p);
    }
}

// ---------------- K3: softmax over S per batch -----------------------------
__global__ void __launch_bounds__(256) k_softmax(float* __restrict__ w_out) {
    __shared__ float red[256];
    const int b   = blockIdx.x;
    const int tid = threadIdx.x;
    const float* sc = g_scores + b * S_;
    float* w = w_out + b * S_;

    float m = -1e30f;
    for (int s = tid; s < S_; s += 256) m = fmaxf(m, sc[s]);
    red[tid] = m; __syncthreads();
    for (int o = 128; o > 0; o >>= 1) {
        if (tid < o) red[tid] = fmaxf(red[tid], red[tid + o]);
        __syncthreads();
    }
    m = red[0];
    __syncthreads();

    float sum = 0.0f;
    for (int s = tid; s < S_; s += 256) {
        float e = expf(sc[s] - m);
        w[s] = e;
        sum += e;
    }
    red[tid] = sum; __syncthreads();
    for (int o = 128; o > 0; o >>= 1) {
        if (tid < o) red[tid] += red[tid + o];
        __syncthreads();
    }
    float inv = 1.0f / red[0];
    for (int s = tid; s < S_; s += 256) w[s] *= inv;
}

// ---------------- K4: context = sum_s w * HS -------------------------------
// grid (8 s-chunks, 64 batches), 256 threads, 4 u's per thread (float4)
__global__ void __launch_bounds__(256) k_context(const float* __restrict__ HS,
                                                 const float* __restrict__ w_in,
                                                 float* __restrict__ ctx) {
    __shared__ float w_sm[256];
    const int tid = threadIdx.x;
    const int b   = blockIdx.y;
    const int s0  = blockIdx.x * 256;

    w_sm[tid] = w_in[b * S_ + s0 + tid];
    __syncthreads();

    const int u = tid * 4;
    float ax = 0.f, ay = 0.f, az = 0.f, aw = 0.f;
    const float* base = HS + ((size_t)b * S_ + s0) * U_ + u;
    for (int s = 0; s < 256; s++) {
        float wv = w_sm[s];
        float4 h = *(const float4*)(base + (size_t)s * U_);
        ax += wv * h.x; ay += wv * h.y; az += wv * h.z; aw += wv * h.w;
    }
    atomicAdd(&ctx[b * U_ + u + 0], ax);
    atomicAdd(&ctx[b * U_ + u + 1], ay);
    atomicAdd(&ctx[b * U_ + u + 2], az);
    atomicAdd(&ctx[b * U_ + u + 3], aw);
}

// ---------------- launch ----------------------------------------------------
extern "C" void kernel_launch(void* const* d_in, const int* in_sizes, int n_in,
                              void* d_out, int out_size) {
    const float* s_prev = (const float*)d_in[0];
    const float* HS     = (const float*)d_in[1];
    const float* Ww     = (const float*)d_in[2];
    const float* Wb     = (const float*)d_in[3];
    const float* Uw     = (const float*)d_in[4];
    const float* Ub     = (const float*)d_in[5];
    const float* Vw     = (const float*)d_in[6];
    const float* Vb     = (const float*)d_in[7];

    float* ctx     = (float*)d_out;            // [64, 1024]
    float* weights = (float*)d_out + B_ * U_;  // [64, 2048, 1]

    k_init<<<M_ / 256, 256>>>(Wb, Vb, ctx);
    k_ws<<<dim3(8, 8), 128>>>(s_prev, Ww);
    k_scores<<<dim3(U_ / BN, M_ / BM), 256>>>(HS, Uw, Ub, Vw);
    k_softmax<<<B_, 256>>>(weights);
    k_context<<<dim3(S_ / 256, B_), 256>>>(HS, weights, ctx);
}

// round 7
// speedup vs baseline: 2.2734x; 2.2734x over previous
#include <cuda_runtime.h>
#include <cuda_bf16.h>
#include <cstdint>
#include <math.h>

#define B_  64
#define S_  2048
#define U_  1024
#define M_  (B_ * S_)   // 131072

// ---------------- scratch (device globals; no allocs allowed) ---------------
__device__ float g_Ws[B_ * U_];                     // s_prev @ W_w + W_b
__device__ float g_scores[M_];                      // pre-softmax scores
__device__ __nv_bfloat16 g_Ahi[(size_t)M_ * U_];    // 256 MB
__device__ __nv_bfloat16 g_Alo[(size_t)M_ * U_];    // 256 MB
__device__ __nv_bfloat16 g_Bhi[U_ * U_];            // Uw^T hi  [n][k]
__device__ __nv_bfloat16 g_Blo[U_ * U_];            // Uw^T lo  [n][k]

// ---------------- K0: init --------------------------------------------------
__global__ void k_init(const float* __restrict__ Wb,
                       const float* __restrict__ Vb,
                       float* __restrict__ ctx_out) {
    int i = blockIdx.x * blockDim.x + threadIdx.x;
    if (i < B_ * U_) { g_Ws[i] = Wb[i & (U_ - 1)]; ctx_out[i] = 0.0f; }
    if (i < M_) g_scores[i] = Vb[0];
}

// ---------------- K1: Ws += s_prev @ W_w ------------------------------------
__global__ void __launch_bounds__(128) k_ws(const float* __restrict__ s_prev,
                                            const float* __restrict__ Ww) {
    __shared__ float s_sm[B_][128];
    const int tid = threadIdx.x;
    const int u   = blockIdx.x * 128 + tid;
    const int k0  = blockIdx.y * 128;
    for (int j = 0; j < 64; j++) {
        int idx = tid + 128 * j;
        s_sm[idx >> 7][idx & 127] = s_prev[(idx >> 7) * U_ + k0 + (idx & 127)];
    }
    __syncthreads();
    float acc[B_];
    #pragma unroll
    for (int b = 0; b < B_; b++) acc[b] = 0.0f;
    for (int kk = 0; kk < 128; kk++) {
        float w = Ww[(k0 + kk) * U_ + u];
        #pragma unroll
        for (int b = 0; b < B_; b++) acc[b] += s_sm[b][kk] * w;
    }
    #pragma unroll
    for (int b = 0; b < B_; b++) atomicAdd(&g_Ws[b * U_ + u], acc[b]);
}

// ---------------- K2a: split HS into bf16 hi/lo ------------------------------
__global__ void __launch_bounds__(256) k_splitA(const float* __restrict__ HS) {
    size_t i = ((size_t)blockIdx.x * 256 + threadIdx.x);
    size_t stride = (size_t)gridDim.x * 256;
    size_t n4 = (size_t)M_ * U_ / 4;
    for (; i < n4; i += stride) {
        float4 v = ((const float4*)HS)[i];
        __nv_bfloat16 h0 = __float2bfloat16(v.x);
        __nv_bfloat16 h1 = __float2bfloat16(v.y);
        __nv_bfloat16 h2 = __float2bfloat16(v.z);
        __nv_bfloat16 h3 = __float2bfloat16(v.w);
        __nv_bfloat16 l0 = __float2bfloat16(v.x - __bfloat162float(h0));
        __nv_bfloat16 l1 = __float2bfloat16(v.y - __bfloat162float(h1));
        __nv_bfloat16 l2 = __float2bfloat16(v.z - __bfloat162float(h2));
        __nv_bfloat16 l3 = __float2bfloat16(v.w - __bfloat162float(h3));
        ((__nv_bfloat162*)g_Ahi)[i * 2]     = __nv_bfloat162(h0, h1);
        ((__nv_bfloat162*)g_Ahi)[i * 2 + 1] = __nv_bfloat162(h2, h3);
        ((__nv_bfloat162*)g_Alo)[i * 2]     = __nv_bfloat162(l0, l1);
        ((__nv_bfloat162*)g_Alo)[i * 2 + 1] = __nv_bfloat162(l2, l3);
    }
}

// ---------------- K2b: transpose+split Uw -> [n][k] --------------------------
__global__ void __launch_bounds__(256) k_splitB(const float* __restrict__ Uw) {
    int i = blockIdx.x * 256 + threadIdx.x;     // 0 .. 1M-1
    int k = i >> 10, n = i & (U_ - 1);
    float x = Uw[k * U_ + n];
    __nv_bfloat16 h = __float2bfloat16(x);
    __nv_bfloat16 l = __float2bfloat16(x - __bfloat162float(h));
    g_Bhi[n * U_ + k] = h;
    g_Blo[n * U_ + k] = l;
}

// ---------------- mma.sync helpers -------------------------------------------
__device__ __forceinline__ uint32_t smem_u32(const void* p) {
    uint32_t a;
    asm("{ .reg .u64 t; cvta.to.shared.u64 t, %1; cvt.u32.u64 %0, t; }"
        : "=r"(a) : "l"(p));
    return a;
}
__device__ __forceinline__ void cp16(uint32_t saddr, const void* g) {
    asm volatile("cp.async.cg.shared.global [%0], [%1], 16;"
                 :: "r"(saddr), "l"(g) : "memory");
}
#define CP_COMMIT() asm volatile("cp.async.commit_group;" ::: "memory")
#define CP_WAIT(N)  asm volatile("cp.async.wait_group %0;" :: "n"(N) : "memory")

__device__ __forceinline__ void mma_bf16(float* c, const uint32_t* a,
                                         uint32_t b0, uint32_t b1) {
    asm volatile(
        "mma.sync.aligned.m16n8k16.row.col.f32.bf16.bf16.f32 "
        "{%0,%1,%2,%3}, {%4,%5,%6,%7}, {%8,%9}, {%0,%1,%2,%3};"
        : "+f"(c[0]), "+f"(c[1]), "+f"(c[2]), "+f"(c[3])
        : "r"(a[0]), "r"(a[1]), "r"(a[2]), "r"(a[3]), "r"(b0), "r"(b1));
}

// ---------------- K3: scores GEMM (bf16x3, mma.sync) -------------------------
// C tile BM=128 x BN=128, BK=32; 8 warps (4m x 2n), warp tile 32x64.
#define BMm 128
#define BNm 128
#define BKm 32
#define RSm 40                 // padded row stride (bf16 elems), 80B
#define TILE_E (BMm * RSm)     // 5120 elems per operand tile
#define SA_H 0
#define SA_L TILE_E
#define SB_H (2 * TILE_E)
#define SB_L (3 * TILE_E)
#define STG_E (4 * TILE_E)     // 20480 elems / 40960 B per stage
#define NCHm (U_ / BKm)        // 32 k-chunks

__global__ void __launch_bounds__(256, 2) k_scores_mma(const float* __restrict__ Ub,
                                                       const float* __restrict__ Vw) {
    extern __shared__ __nv_bfloat16 sm[];          // 2 stages = 81920 B
    __shared__ float sWs[BNm], sUb[BNm], sVw[BNm];

    const int tid  = threadIdx.x;
    const int wid  = tid >> 5;
    const int lane = tid & 31;
    const int gid  = lane >> 2;
    const int tig  = lane & 3;
    const int warp_m = wid & 3;                    // 0..3, 32 rows each
    const int warp_n = wid >> 2;                   // 0..1, 64 cols each

    const int col0 = blockIdx.x * BNm;
    const int row0 = blockIdx.y * BMm;
    const int b    = row0 >> 11;                   // batch (S=2048)

    if (tid < BNm) {
        sWs[tid] = g_Ws[b * U_ + col0 + tid];
        sUb[tid] = Ub[col0 + tid];
        sVw[tid] = Vw[col0 + tid];
    }

    const __nv_bfloat16* gAh = g_Ahi + (size_t)row0 * U_;
    const __nv_bfloat16* gAl = g_Alo + (size_t)row0 * U_;
    const __nv_bfloat16* gBh = g_Bhi + (size_t)col0 * U_;
    const __nv_bfloat16* gBl = g_Blo + (size_t)col0 * U_;

    const uint32_t sb = smem_u32(sm);

    // issue cp.async for chunk kc into stage buf (each tile: 512 x 16B chunks)
    auto issue = [&](int kc, int buf) {
        const int kofs = kc * BKm;
        const uint32_t stb = sb + (buf * STG_E) * 2;
        #pragma unroll
        for (int i = 0; i < 2; i++) {
            int c = tid + i * 256;                 // 0..511
            int r = c >> 2, q = (c & 3) * 8;       // row, elem offset
            uint32_t so = (uint32_t)(r * RSm + q) * 2;
            cp16(stb + SA_H * 2 + so, gAh + (size_t)r * U_ + kofs + q);
            cp16(stb + SA_L * 2 + so, gAl + (size_t)r * U_ + kofs + q);
            cp16(stb + SB_H * 2 + so, gBh + (size_t)r * U_ + kofs + q);
            cp16(stb + SB_L * 2 + so, gBl + (size_t)r * U_ + kofs + q);
        }
        CP_COMMIT();
    };

    float acc[2][8][4];
    #pragma unroll
    for (int mt = 0; mt < 2; mt++)
        #pragma unroll
        for (int nt = 0; nt < 8; nt++)
            #pragma unroll
            for (int j = 0; j < 4; j++) acc[mt][nt][j] = 0.0f;

    issue(0, 0);

    for (int kc = 0; kc < NCHm; kc++) {
        if (kc + 1 < NCHm) { issue(kc + 1, (kc + 1) & 1); CP_WAIT(1); }
        else               { CP_WAIT(0); }
        __syncthreads();

        const __nv_bfloat16* s = sm + (kc & 1) * STG_E;
        #pragma unroll
        for (int slab = 0; slab < 2; slab++) {
            const int kb = slab * 16;
            uint32_t Ah[2][4], Al[2][4];
            #pragma unroll
            for (int mt = 0; mt < 2; mt++) {
                int r = warp_m * 32 + mt * 16 + gid;
                const __nv_bfloat16* pah = s + SA_H + r * RSm + kb + 2 * tig;
                const __nv_bfloat16* pal = s + SA_L + r * RSm + kb + 2 * tig;
                Ah[mt][0] = *(const uint32_t*)(pah);
                Ah[mt][1] = *(const uint32_t*)(pah + 8 * RSm);
                Ah[mt][2] = *(const uint32_t*)(pah + 8);
                Ah[mt][3] = *(const uint32_t*)(pah + 8 * RSm + 8);
                Al[mt][0] = *(const uint32_t*)(pal);
                Al[mt][1] = *(const uint32_t*)(pal + 8 * RSm);
                Al[mt][2] = *(const uint32_t*)(pal + 8);
                Al[mt][3] = *(const uint32_t*)(pal + 8 * RSm + 8);
            }
            #pragma unroll
            for (int nt = 0; nt < 8; nt++) {
                int n = warp_n * 64 + nt * 8 + gid;
                const __nv_bfloat16* pbh = s + SB_H + n * RSm + kb + 2 * tig;
                const __nv_bfloat16* pbl = s + SB_L + n * RSm + kb + 2 * tig;
                uint32_t bh0 = *(const uint32_t*)(pbh);
                uint32_t bh1 = *(const uint32_t*)(pbh + 8);
                uint32_t bl0 = *(const uint32_t*)(pbl);
                uint32_t bl1 = *(const uint32_t*)(pbl + 8);
                #pragma unroll
                for (int mt = 0; mt < 2; mt++) mma_bf16(acc[mt][nt], Ah[mt], bh0, bh1);
                #pragma unroll
                for (int mt = 0; mt < 2; mt++) mma_bf16(acc[mt][nt], Ah[mt], bl0, bl1);
                #pragma unroll
                for (int mt = 0; mt < 2; mt++) mma_bf16(acc[mt][nt], Al[mt], bh0, bh1);
            }
        }
        __syncthreads();
    }

    // epilogue: tanh + dot with Vw, reduce over n within thread, then over tig
    #pragma unroll
    for (int mt = 0; mt < 2; mt++) {
        float pl = 0.0f, ph = 0.0f;
        #pragma unroll
        for (int nt = 0; nt < 8; nt++) {
            int nb = warp_n * 64 + nt * 8 + 2 * tig;
            pl += tanhf(acc[mt][nt][0] + sWs[nb]     + sUb[nb])     * sVw[nb];
            pl += tanhf(acc[mt][nt][1] + sWs[nb + 1] + sUb[nb + 1]) * sVw[nb + 1];
            ph += tanhf(acc[mt][nt][2] + sWs[nb]     + sUb[nb])     * sVw[nb];
            ph += tanhf(acc[mt][nt][3] + sWs[nb + 1] + sUb[nb + 1]) * sVw[nb + 1];
        }
        pl += __shfl_xor_sync(0xffffffffu, pl, 1);
        pl += __shfl_xor_sync(0xffffffffu, pl, 2);
        ph += __shfl_xor_sync(0xffffffffu, ph, 1);
        ph += __shfl_xor_sync(0xffffffffu, ph, 2);
        if (tig == 0) {
            int r = row0 + warp_m * 32 + mt * 16 + gid;
            atomicAdd(&g_scores[r], pl);
            atomicAdd(&g_scores[r + 8], ph);
        }
    }
}

// ---------------- K4: softmax over S per batch -------------------------------
__global__ void __launch_bounds__(256) k_softmax(float* __restrict__ w_out) {
    __shared__ float red[256];
    const int b   = blockIdx.x;
    const int tid = threadIdx.x;
    const float* sc = g_scores + b * S_;
    float* w = w_out + b * S_;

    float m = -1e30f;
    for (int s = tid; s < S_; s += 256) m = fmaxf(m, sc[s]);
    red[tid] = m; __syncthreads();
    for (int o = 128; o > 0; o >>= 1) {
        if (tid < o) red[tid] = fmaxf(red[tid], red[tid + o]);
        __syncthreads();
    }
    m = red[0];
    __syncthreads();

    float sum = 0.0f;
    for (int s = tid; s < S_; s += 256) {
        float e = expf(sc[s] - m);
        w[s] = e;
        sum += e;
    }
    red[tid] = sum; __syncthreads();
    for (int o = 128; o > 0; o >>= 1) {
        if (tid < o) red[tid] += red[tid + o];
        __syncthreads();
    }
    float inv = 1.0f / red[0];
    for (int s = tid; s < S_; s += 256) w[s] *= inv;
}

// ---------------- K5: context = sum_s w * HS ---------------------------------
__global__ void __launch_bounds__(256) k_context(const float* __restrict__ HS,
                                                 const float* __restrict__ w_in,
                                                 float* __restrict__ ctx) {
    __shared__ float w_sm[256];
    const int tid = threadIdx.x;
    const int b   = blockIdx.y;
    const int s0  = blockIdx.x * 256;

    w_sm[tid] = w_in[b * S_ + s0 + tid];
    __syncthreads();

    const int u = tid * 4;
    float ax = 0.f, ay = 0.f, az = 0.f, aw = 0.f;
    const float* base = HS + ((size_t)b * S_ + s0) * U_ + u;
    for (int s = 0; s < 256; s++) {
        float wv = w_sm[s];
        float4 h = *(const float4*)(base + (size_t)s * U_);
        ax += wv * h.x; ay += wv * h.y; az += wv * h.z; aw += wv * h.w;
    }
    atomicAdd(&ctx[b * U_ + u + 0], ax);
    atomicAdd(&ctx[b * U_ + u + 1], ay);
    atomicAdd(&ctx[b * U_ + u + 2], az);
    atomicAdd(&ctx[b * U_ + u + 3], aw);
}

// ---------------- launch -----------------------------------------------------
extern "C" void kernel_launch(void* const* d_in, const int* in_sizes, int n_in,
                              void* d_out, int out_size) {
    const float* s_prev = (const float*)d_in[0];
    const float* HS     = (const float*)d_in[1];
    const float* Ww     = (const float*)d_in[2];
    const float* Wb     = (const float*)d_in[3];
    const float* Uw     = (const float*)d_in[4];
    const float* Ub     = (const float*)d_in[5];
    const float* Vw     = (const float*)d_in[6];
    const float* Vb     = (const float*)d_in[7];

    float* ctx     = (float*)d_out;            // [64, 1024]
    float* weights = (float*)d_out + B_ * U_;  // [64, 2048, 1]

    const int smem_bytes = 2 * STG_E * 2;      // 81920
    cudaFuncSetAttribute(k_scores_mma,
                         cudaFuncAttributeMaxDynamicSharedMemorySize, smem_bytes);

    k_init<<<M_ / 256, 256>>>(Wb, Vb, ctx);
    k_ws<<<dim3(8, 8), 128>>>(s_prev, Ww);
    k_splitA<<<8192, 256>>>(HS);
    k_splitB<<<U_ * U_ / 256, 256>>>(Uw);
    k_scores_mma<<<dim3(U_ / BNm, M_ / BMm), 256, smem_bytes>>>(Ub, Vw);
    k_softmax<<<B_, 256>>>(weights);
    k_context<<<dim3(S_ / 256, B_), 256>>>(HS, weights, ctx);
}

// round 8
// speedup vs baseline: 2.3626x; 1.0392x over previous
#include <cuda_runtime.h>
#include <cuda_bf16.h>
#include <cstdint>
#include <math.h>

#define B_  64
#define S_  2048
#define U_  1024
#define M_  (B_ * S_)   // 131072

// ---------------- scratch (device globals; no allocs allowed) ---------------
__device__ float g_Ws[B_ * U_];                     // s_prev @ W_w + W_b
__device__ float g_scores[M_];                      // pre-softmax scores
__device__ __nv_bfloat16 g_Bhi[U_ * U_];            // Uw^T hi  [n][k]
__device__ __nv_bfloat16 g_Blo[U_ * U_];            // Uw^T lo  [n][k]

// ---------------- K0: init --------------------------------------------------
__global__ void k_init(const float* __restrict__ Wb,
                       const float* __restrict__ Vb,
                       float* __restrict__ ctx_out) {
    int i = blockIdx.x * blockDim.x + threadIdx.x;
    if (i < B_ * U_) { g_Ws[i] = Wb[i & (U_ - 1)]; ctx_out[i] = 0.0f; }
    if (i < M_) g_scores[i] = Vb[0];
}

// ---------------- K1: Ws += s_prev @ W_w ------------------------------------
__global__ void __launch_bounds__(128) k_ws(const float* __restrict__ s_prev,
                                            const float* __restrict__ Ww) {
    __shared__ float s_sm[B_][128];
    const int tid = threadIdx.x;
    const int u   = blockIdx.x * 128 + tid;
    const int k0  = blockIdx.y * 128;
    for (int j = 0; j < 64; j++) {
        int idx = tid + 128 * j;
        s_sm[idx >> 7][idx & 127] = s_prev[(idx >> 7) * U_ + k0 + (idx & 127)];
    }
    __syncthreads();
    float acc[B_];
    #pragma unroll
    for (int b = 0; b < B_; b++) acc[b] = 0.0f;
    for (int kk = 0; kk < 128; kk++) {
        float w = Ww[(k0 + kk) * U_ + u];
        #pragma unroll
        for (int b = 0; b < B_; b++) acc[b] += s_sm[b][kk] * w;
    }
    #pragma unroll
    for (int b = 0; b < B_; b++) atomicAdd(&g_Ws[b * U_ + u], acc[b]);
}

// ---------------- K2: transpose+split Uw -> [n][k] ---------------------------
__global__ void __launch_bounds__(256) k_splitB(const float* __restrict__ Uw) {
    int i = blockIdx.x * 256 + threadIdx.x;     // 0 .. 1M-1
    int k = i >> 10, n = i & (U_ - 1);
    float x = Uw[k * U_ + n];
    __nv_bfloat16 h = __float2bfloat16(x);
    __nv_bfloat16 l = __float2bfloat16(x - __bfloat162float(h));
    g_Bhi[n * U_ + k] = h;
    g_Blo[n * U_ + k] = l;
}

// ---------------- mma.sync helpers -------------------------------------------
__device__ __forceinline__ uint32_t smem_u32(const void* p) {
    uint32_t a;
    asm("{ .reg .u64 t; cvta.to.shared.u64 t, %1; cvt.u32.u64 %0, t; }"
        : "=r"(a) : "l"(p));
    return a;
}
__device__ __forceinline__ void cp16(uint32_t saddr, const void* g) {
    asm volatile("cp.async.cg.shared.global [%0], [%1], 16;"
                 :: "r"(saddr), "l"(g) : "memory");
}
#define CP_COMMIT() asm volatile("cp.async.commit_group;" ::: "memory")
#define CP_WAIT(N)  asm volatile("cp.async.wait_group %0;" :: "n"(N) : "memory")

__device__ __forceinline__ void mma_bf16(float* c, const uint32_t* a,
                                         uint32_t b0, uint32_t b1) {
    asm volatile(
        "mma.sync.aligned.m16n8k16.row.col.f32.bf16.bf16.f32 "
        "{%0,%1,%2,%3}, {%4,%5,%6,%7}, {%8,%9}, {%0,%1,%2,%3};"
        : "+f"(c[0]), "+f"(c[1]), "+f"(c[2]), "+f"(c[3])
        : "r"(a[0]), "r"(a[1]), "r"(a[2]), "r"(a[3]), "r"(b0), "r"(b1));
}

// pack 2 fp32 -> bf16x2 (hi), and residual bf16x2 (lo)
__device__ __forceinline__ void split2(float x0, float x1, uint32_t& hi, uint32_t& lo) {
    __nv_bfloat162 h = __floats2bfloat162_rn(x0, x1);
    hi = *(uint32_t*)&h;
    __nv_bfloat162 l = __floats2bfloat162_rn(x0 - __low2float(h), x1 - __high2float(h));
    lo = *(uint32_t*)&l;
}

// ---------------- K3: scores GEMM (bf16x3, mma.sync, in-reg A split) ---------
// C tile BM=128 x BN=128, BK=32; 8 warps (4m x 2n), warp tile 32x64.
#define BMm 128
#define BNm 128
#define BKm 32
// A: fp32 in SMEM, padded row stride 36 floats (144 B)
#define RSA 36
#define A_E  (BMm * RSA)            // 4608 floats
// B: bf16 in SMEM, padded row stride 40 bf16 (80 B)
#define RSB 40
#define B_E  (BNm * RSB)            // 5120 bf16
// stage layout (bytes): [A fp32 18432][Bhi 10240][Blo 10240] = 38912 B
#define STG_B   (A_E * 4 + 2 * B_E * 2)
#define OFF_BH  (A_E * 4)
#define OFF_BL  (A_E * 4 + B_E * 2)
#define NCHm (U_ / BKm)             // 32 k-chunks

__global__ void __launch_bounds__(256, 2) k_scores_mma(const float* __restrict__ HS,
                                                       const float* __restrict__ Ub,
                                                       const float* __restrict__ Vw) {
    extern __shared__ char sm[];                   // 2 stages
    __shared__ float sWs[BNm], sUb[BNm], sVw[BNm];

    const int tid  = threadIdx.x;
    const int wid  = tid >> 5;
    const int lane = tid & 31;
    const int gid  = lane >> 2;
    const int tig  = lane & 3;
    const int warp_m = wid & 3;                    // 0..3, 32 rows each
    const int warp_n = wid >> 2;                   // 0..1, 64 cols each

    const int col0 = blockIdx.x * BNm;
    const int row0 = blockIdx.y * BMm;
    const int b    = row0 >> 11;                   // batch (S=2048)

    if (tid < BNm) {
        sWs[tid] = g_Ws[b * U_ + col0 + tid];
        sUb[tid] = Ub[col0 + tid];
        sVw[tid] = Vw[col0 + tid];
    }

    const float* gA = HS + (size_t)row0 * U_;
    const __nv_bfloat16* gBh = g_Bhi + (size_t)col0 * U_;
    const __nv_bfloat16* gBl = g_Blo + (size_t)col0 * U_;

    const uint32_t sb = smem_u32(sm);

    // issue cp.async for chunk kc into stage buf
    // A: 128 rows x 128 B = 1024 cp16 (4/thread); B hi+lo: 128 rows x 64 B each = 512 cp16 (2/thread)
    auto issue = [&](int kc, int buf) {
        const int kofs = kc * BKm;
        const uint32_t stb = sb + buf * STG_B;
        #pragma unroll
        for (int i = 0; i < 4; i++) {
            int c = tid + i * 256;                 // 0..1023
            int r = c >> 3, q = (c & 7) * 4;       // row, float offset
            cp16(stb + (uint32_t)(r * RSA + q) * 4, gA + (size_t)r * U_ + kofs + q);
        }
        #pragma unroll
        for (int i = 0; i < 2; i++) {
            int c = tid + i * 256;                 // 0..511
            int r = c >> 2, q = (c & 3) * 8;       // row, bf16 offset
            uint32_t so = (uint32_t)(r * RSB + q) * 2;
            cp16(stb + OFF_BH + so, gBh + (size_t)r * U_ + kofs + q);
            cp16(stb + OFF_BL + so, gBl + (size_t)r * U_ + kofs + q);
        }
        CP_COMMIT();
    };

    float acc[2][8][4];
    #pragma unroll
    for (int mt = 0; mt < 2; mt++)
        #pragma unroll
        for (int nt = 0; nt < 8; nt++)
            #pragma unroll
            for (int j = 0; j < 4; j++) acc[mt][nt][j] = 0.0f;

    issue(0, 0);

    for (int kc = 0; kc < NCHm; kc++) {
        if (kc + 1 < NCHm) { issue(kc + 1, (kc + 1) & 1); CP_WAIT(1); }
        else               { CP_WAIT(0); }
        __syncthreads();

        const char* st = sm + (kc & 1) * STG_B;
        const float* sA = (const float*)st;
        const __nv_bfloat16* sBh = (const __nv_bfloat16*)(st + OFF_BH);
        const __nv_bfloat16* sBl = (const __nv_bfloat16*)(st + OFF_BL);

        #pragma unroll
        for (int slab = 0; slab < 2; slab++) {
            const int kb = slab * 16;
            uint32_t Ah[2][4], Al[2][4];
            #pragma unroll
            for (int mt = 0; mt < 2; mt++) {
                int r = warp_m * 32 + mt * 16 + gid;
                const float* pa = sA + r * RSA + kb + 2 * tig;
                float2 v0 = *(const float2*)(pa);
                float2 v1 = *(const float2*)(pa + 8 * RSA);
                float2 v2 = *(const float2*)(pa + 8);
                float2 v3 = *(const float2*)(pa + 8 * RSA + 8);
                split2(v0.x, v0.y, Ah[mt][0], Al[mt][0]);
                split2(v1.x, v1.y, Ah[mt][1], Al[mt][1]);
                split2(v2.x, v2.y, Ah[mt][2], Al[mt][2]);
                split2(v3.x, v3.y, Ah[mt][3], Al[mt][3]);
            }
            #pragma unroll
            for (int nt = 0; nt < 8; nt++) {
                int n = warp_n * 64 + nt * 8 + gid;
                const __nv_bfloat16* pbh = sBh + n * RSB + kb + 2 * tig;
                const __nv_bfloat16* pbl = sBl + n * RSB + kb + 2 * tig;
                uint32_t bh0 = *(const uint32_t*)(pbh);
                uint32_t bh1 = *(const uint32_t*)(pbh + 8);
                uint32_t bl0 = *(const uint32_t*)(pbl);
                uint32_t bl1 = *(const uint32_t*)(pbl + 8);
                #pragma unroll
                for (int mt = 0; mt < 2; mt++) mma_bf16(acc[mt][nt], Ah[mt], bh0, bh1);
                #pragma unroll
                for (int mt = 0; mt < 2; mt++) mma_bf16(acc[mt][nt], Ah[mt], bl0, bl1);
                #pragma unroll
                for (int mt = 0; mt < 2; mt++) mma_bf16(acc[mt][nt], Al[mt], bh0, bh1);
            }
        }
        __syncthreads();
    }

    // epilogue: tanh + dot with Vw, reduce over n within thread, then over tig
    #pragma unroll
    for (int mt = 0; mt < 2; mt++) {
        float pl = 0.0f, ph = 0.0f;
        #pragma unroll
        for (int nt = 0; nt < 8; nt++) {
            int nb = warp_n * 64 + nt * 8 + 2 * tig;
            pl += tanhf(acc[mt][nt][0] + sWs[nb]     + sUb[nb])     * sVw[nb];
            pl += tanhf(acc[mt][nt][1] + sWs[nb + 1] + sUb[nb + 1]) * sVw[nb + 1];
            ph += tanhf(acc[mt][nt][2] + sWs[nb]     + sUb[nb])     * sVw[nb];
            ph += tanhf(acc[mt][nt][3] + sWs[nb + 1] + sUb[nb + 1]) * sVw[nb + 1];
        }
        pl += __shfl_xor_sync(0xffffffffu, pl, 1);
        pl += __shfl_xor_sync(0xffffffffu, pl, 2);
        ph += __shfl_xor_sync(0xffffffffu, ph, 1);
        ph += __shfl_xor_sync(0xffffffffu, ph, 2);
        if (tig == 0) {
            int r = row0 + warp_m * 32 + mt * 16 + gid;
            atomicAdd(&g_scores[r], pl);
            atomicAdd(&g_scores[r + 8], ph);
        }
    }
}

// ---------------- K4: softmax over S per batch -------------------------------
__global__ void __launch_bounds__(256) k_softmax(float* __restrict__ w_out) {
    __shared__ float red[256];
    const int b   = blockIdx.x;
    const int tid = threadIdx.x;
    const float* sc = g_scores + b * S_;
    float* w = w_out + b * S_;

    float m = -1e30f;
    for (int s = tid; s < S_; s += 256) m = fmaxf(m, sc[s]);
    red[tid] = m; __syncthreads();
    for (int o = 128; o > 0; o >>= 1) {
        if (tid < o) red[tid] = fmaxf(red[tid], red[tid + o]);
        __syncthreads();
    }
    m = red[0];
    __syncthreads();

    float sum = 0.0f;
    for (int s = tid; s < S_; s += 256) {
        float e = expf(sc[s] - m);
        w[s] = e;
        sum += e;
    }
    red[tid] = sum; __syncthreads();
    for (int o = 128; o > 0; o >>= 1) {
        if (tid < o) red[tid] += red[tid + o];
        __syncthreads();
    }
    float inv = 1.0f / red[0];
    for (int s = tid; s < S_; s += 256) w[s] *= inv;
}

// ---------------- K5: context = sum_s w * HS ---------------------------------
__global__ void __launch_bounds__(256) k_context(const float* __restrict__ HS,
                                                 const float* __restrict__ w_in,
                                                 float* __restrict__ ctx) {
    __shared__ float w_sm[256];
    const int tid = threadIdx.x;
    const int b   = blockIdx.y;
    const int s0  = blockIdx.x * 256;

    w_sm[tid] = w_in[b * S_ + s0 + tid];
    __syncthreads();

    const int u = tid * 4;
    float ax = 0.f, ay = 0.f, az = 0.f, aw = 0.f;
    const float* base = HS + ((size_t)b * S_ + s0) * U_ + u;
    for (int s = 0; s < 256; s++) {
        float wv = w_sm[s];
        float4 h = *(const float4*)(base + (size_t)s * U_);
        ax += wv * h.x; ay += wv * h.y; az += wv * h.z; aw += wv * h.w;
    }
    atomicAdd(&ctx[b * U_ + u + 0], ax);
    atomicAdd(&ctx[b * U_ + u + 1], ay);
    atomicAdd(&ctx[b * U_ + u + 2], az);
    atomicAdd(&ctx[b * U_ + u + 3], aw);
}

// ---------------- launch -----------------------------------------------------
extern "C" void kernel_launch(void* const* d_in, const int* in_sizes, int n_in,
                              void* d_out, int out_size) {
    const float* s_prev = (const float*)d_in[0];
    const float* HS     = (const float*)d_in[1];
    const float* Ww     = (const float*)d_in[2];
    const float* Wb     = (const float*)d_in[3];
    const float* Uw     = (const float*)d_in[4];
    const float* Ub     = (const float*)d_in[5];
    const float* Vw     = (const float*)d_in[6];
    const float* Vb     = (const float*)d_in[7];

    float* ctx     = (float*)d_out;            // [64, 1024]
    float* weights = (float*)d_out + B_ * U_;  // [64, 2048, 1]

    const int smem_bytes = 2 * STG_B;          // 77824
    cudaFuncSetAttribute(k_scores_mma,
                         cudaFuncAttributeMaxDynamicSharedMemorySize, smem_bytes);

    // launch order chosen so the profiler's captured launch (#4) is the GEMM
    k_init<<<M_ / 256, 256>>>(Wb, Vb, ctx);
    k_ws<<<dim3(8, 8), 128>>>(s_prev, Ww);
    k_splitB<<<U_ * U_ / 256, 256>>>(Uw);
    k_scores_mma<<<dim3(U_ / BNm, M_ / BMm), 256, smem_bytes>>>(HS, Ub, Vw);
    k_softmax<<<B_, 256>>>(weights);
    k_context<<<dim3(S_ / 256, B_), 256>>>(HS, weights, ctx);
}